// round 1
// baseline (speedup 1.0000x reference)
#include <cuda_runtime.h>
#include <cuda_bf16.h>
#include <cstdint>
#include <math.h>

#define BATCH 8192
#define DIM   256
#define BM    64
#define BN    128
#define THREADS 256
#define INV_TEMP 1000.0f

// ---------------- device globals (no allocation allowed) ----------------
__device__ __nv_bfloat16 g_zi[BATCH * DIM];
__device__ __nv_bfloat16 g_zj[BATCH * DIM];
__device__ float g_diag[BATCH];
__device__ float g_diag_sum;
__device__ float g_loss_sum;

// ---------------- init ----------------
__global__ void cl_init_kernel() {
    g_diag_sum = 0.0f;
    g_loss_sum = 0.0f;
}

// ---------------- normalize + bf16 convert + exact fp32 diagonal ----------------
// one block per row, 256 threads (DIM == 256)
__global__ void cl_prep_kernel(const float* __restrict__ p1,
                               const float* __restrict__ p2) {
    int row = blockIdx.x;
    int t = threadIdx.x;

    float v1 = p1[row * DIM + t];
    float v2 = p2[row * DIM + t];

    float s1 = v1 * v1;
    float s2 = v2 * v2;
    float s3 = v1 * v2;

    // warp reduce
    #pragma unroll
    for (int o = 16; o > 0; o >>= 1) {
        s1 += __shfl_down_sync(0xffffffffu, s1, o);
        s2 += __shfl_down_sync(0xffffffffu, s2, o);
        s3 += __shfl_down_sync(0xffffffffu, s3, o);
    }

    __shared__ float sh1[8], sh2[8], sh3[8];
    __shared__ float rn1, rn2, rdot;
    int wid = t >> 5;
    if ((t & 31) == 0) { sh1[wid] = s1; sh2[wid] = s2; sh3[wid] = s3; }
    __syncthreads();
    if (t == 0) {
        float a = 0.f, b = 0.f, c = 0.f;
        #pragma unroll
        for (int i = 0; i < 8; i++) { a += sh1[i]; b += sh2[i]; c += sh3[i]; }
        rn1 = fmaxf(sqrtf(a), 1e-12f);
        rn2 = fmaxf(sqrtf(b), 1e-12f);
        rdot = c;
    }
    __syncthreads();

    float n1 = rn1, n2 = rn2;
    g_zi[row * DIM + t] = __float2bfloat16(v1 / n1);
    g_zj[row * DIM + t] = __float2bfloat16(v2 / n2);

    if (t == 0) {
        float d = rdot / (n1 * n2);   // exact fp32 cosine of the positive pair
        g_diag[row] = d;
        atomicAdd(&g_diag_sum, d);
    }
}

// ---------------- fused GEMM + online LSE ----------------
// smem: As 64x256 bf16 (swizzled)  = 32768 B
//       Bs 128x256 bf16 (swizzled) = 65536 B
//       red_m/red_s 64x4 floats x2 =  2048 B
#define SMEM_BYTES (32768 + 65536 + 2048)

__device__ __forceinline__ void ldsm_x4(uint32_t* r, uint32_t addr) {
    asm volatile("ldmatrix.sync.aligned.m8n8.x4.shared.b16 {%0,%1,%2,%3}, [%4];\n"
                 : "=r"(r[0]), "=r"(r[1]), "=r"(r[2]), "=r"(r[3])
                 : "r"(addr));
}

__device__ __forceinline__ void mma_bf16(float* d, const uint32_t* a, const uint32_t* b) {
    asm volatile(
        "mma.sync.aligned.m16n8k16.row.col.f32.bf16.bf16.f32 "
        "{%0,%1,%2,%3}, {%4,%5,%6,%7}, {%8,%9}, {%0,%1,%2,%3};\n"
        : "+f"(d[0]), "+f"(d[1]), "+f"(d[2]), "+f"(d[3])
        : "r"(a[0]), "r"(a[1]), "r"(a[2]), "r"(a[3]), "r"(b[0]), "r"(b[1]));
}

__global__ void __launch_bounds__(THREADS, 1)
cl_main_kernel() {
    extern __shared__ char smem[];
    char* Asm = smem;                 // 64 rows x 512 B, 16B-chunk swizzled
    char* Bsm = smem + 32768;         // 128 rows x 512 B
    float* red_m = (float*)(smem + 32768 + 65536);   // [64][4]
    float* red_s = red_m + 256;                       // [64][4]

    const int tid  = threadIdx.x;
    const int lane = tid & 31;
    const int warp = tid >> 5;
    const int warp_m = warp >> 2;     // 0..1  (32 rows each)
    const int warp_n = warp & 3;      // 0..3  (32 cols each)
    const int rb = blockIdx.x * BM;

    uint32_t as_base = (uint32_t)__cvta_generic_to_shared(Asm);
    uint32_t bs_base = (uint32_t)__cvta_generic_to_shared(Bsm);

    // ---- load A tile (64 rows x 256 bf16) once, swizzled ----
    {
        const uint4* src = (const uint4*)g_zi;
        #pragma unroll
        for (int i = tid; i < BM * 32; i += THREADS) {
            int r = i >> 5, c = i & 31;
            uint4 v = src[(size_t)(rb + r) * 32 + c];
            *(uint4*)(Asm + r * 512 + ((c ^ (r & 7)) << 4)) = v;
        }
    }

    // online LSE state: 4 row-instances per thread (mi in 0..1, half in 0..1)
    float m_run[4], s_run[4];
    #pragma unroll
    for (int i = 0; i < 4; i++) { m_run[i] = -1e30f; s_run[i] = 0.0f; }

    for (int cb = 0; cb < BATCH; cb += BN) {
        __syncthreads();   // previous compute finished reading Bs
        // ---- load B tile (128 rows of z_j x 256 bf16), swizzled ----
        {
            const uint4* src = (const uint4*)g_zj;
            #pragma unroll
            for (int i = tid; i < BN * 32; i += THREADS) {
                int r = i >> 5, c = i & 31;
                uint4 v = src[(size_t)(cb + r) * 32 + c];
                *(uint4*)(Bsm + r * 512 + ((c ^ (r & 7)) << 4)) = v;
            }
        }
        __syncthreads();

        float acc[2][4][4];
        #pragma unroll
        for (int mi = 0; mi < 2; mi++)
            #pragma unroll
            for (int ni = 0; ni < 4; ni++)
                #pragma unroll
                for (int q = 0; q < 4; q++)
                    acc[mi][ni][q] = 0.0f;

        #pragma unroll
        for (int ks = 0; ks < 16; ks++) {
            uint32_t a[2][4];
            #pragma unroll
            for (int mi = 0; mi < 2; mi++) {
                int row = warp_m * 32 + mi * 16 + (lane & 15);
                int ch  = ks * 2 + (lane >> 4);
                ldsm_x4(a[mi], as_base + row * 512 + ((ch ^ (row & 7)) << 4));
            }
            uint32_t b[4][2];
            #pragma unroll
            for (int np = 0; np < 2; np++) {
                int col = warp_n * 32 + np * 16 + (lane & 7) + ((lane >> 4) << 3);
                int ch  = ks * 2 + ((lane >> 3) & 1);
                uint32_t r4[4];
                ldsm_x4(r4, bs_base + col * 512 + ((ch ^ (col & 7)) << 4));
                b[np * 2][0] = r4[0];     b[np * 2][1] = r4[1];
                b[np * 2 + 1][0] = r4[2]; b[np * 2 + 1][1] = r4[3];
            }
            #pragma unroll
            for (int mi = 0; mi < 2; mi++)
                #pragma unroll
                for (int ni = 0; ni < 4; ni++)
                    mma_bf16(acc[mi][ni], a[mi], b[ni]);
        }

        // ---- online LSE update for this 64x128 tile ----
        #pragma unroll
        for (int mi = 0; mi < 2; mi++) {
            #pragma unroll
            for (int h = 0; h < 2; h++) {
                int idx = mi * 2 + h;
                float y[8];
                #pragma unroll
                for (int ni = 0; ni < 4; ni++) {
                    y[ni * 2]     = acc[mi][ni][h * 2]     * INV_TEMP;
                    y[ni * 2 + 1] = acc[mi][ni][h * 2 + 1] * INV_TEMP;
                }
                float tm = y[0];
                #pragma unroll
                for (int j = 1; j < 8; j++) tm = fmaxf(tm, y[j]);
                tm = fmaxf(tm, __shfl_xor_sync(0xffffffffu, tm, 1));
                tm = fmaxf(tm, __shfl_xor_sync(0xffffffffu, tm, 2));
                float ts = 0.0f;
                #pragma unroll
                for (int j = 0; j < 8; j++) ts += __expf(y[j] - tm);
                ts += __shfl_xor_sync(0xffffffffu, ts, 1);
                ts += __shfl_xor_sync(0xffffffffu, ts, 2);
                float nm = fmaxf(m_run[idx], tm);
                s_run[idx] = s_run[idx] * __expf(m_run[idx] - nm)
                           + ts * __expf(tm - nm);
                m_run[idx] = nm;
            }
        }
    }

    // ---- merge the 4 column-slice partials per row, finish loss ----
    #pragma unroll
    for (int idx = 0; idx < 4; idx++) {
        int row_local = warp_m * 32 + (idx >> 1) * 16 + (idx & 1) * 8 + (lane >> 2);
        if ((lane & 3) == 0) {
            red_m[row_local * 4 + warp_n] = m_run[idx];
            red_s[row_local * 4 + warp_n] = s_run[idx];
        }
    }
    __syncthreads();

    if (tid < BM) {
        int row = tid;
        float m = red_m[row * 4 + 0];
        #pragma unroll
        for (int w = 1; w < 4; w++) m = fmaxf(m, red_m[row * 4 + w]);
        float s = 0.0f;
        #pragma unroll
        for (int w = 0; w < 4; w++)
            s += red_s[row * 4 + w] * __expf(red_m[row * 4 + w] - m);
        float lse = m + logf(s);
        float loss_row = lse - INV_TEMP * g_diag[rb + row];
        atomicAdd(&g_loss_sum, loss_row);
    }
}

// ---------------- finalize ----------------
__global__ void cl_fin_kernel(float* out, int out_size) {
    if (out_size > 0) out[0] = g_loss_sum / (float)BATCH;
    if (out_size > 1) out[1] = g_diag_sum;
}

// ---------------- launch ----------------
extern "C" void kernel_launch(void* const* d_in, const int* in_sizes, int n_in,
                              void* d_out, int out_size) {
    const float* p1 = (const float*)d_in[0];
    const float* p2 = (const float*)d_in[1];
    float* out = (float*)d_out;

    cudaFuncSetAttribute(cl_main_kernel,
                         cudaFuncAttributeMaxDynamicSharedMemorySize, SMEM_BYTES);

    cl_init_kernel<<<1, 1>>>();
    cl_prep_kernel<<<BATCH, DIM>>>(p1, p2);
    cl_main_kernel<<<BATCH / BM, THREADS, SMEM_BYTES>>>();
    cl_fin_kernel<<<1, 1>>>(out, out_size);
}

// round 3
// speedup vs baseline: 1.6522x; 1.6522x over previous
#include <cuda_runtime.h>
#include <cuda_bf16.h>
#include <cstdint>
#include <math.h>

#define BATCH 8192
#define DIM   256
#define BM    128
#define BN    128
#define COLSPER 4096
#define TILES (COLSPER / BN)      // 32
#define THREADS 256

#define SCALE_L2 1442.6950408889634f   // 1000 * log2(e)
#define LN2F     0.69314718055994531f

// ---- shared memory layout (dynamic) ----
#define SA     0                        // A tile 128x256 bf16 (64KB, swizzled)
#define SB0    65536                    // B tile buf0 (64KB)
#define SB1    131072                   // B tile buf1 (64KB)
#define SMRG_M 196608                   // 128*4 floats (2KB)
#define SMRG_S 198656                   // 128*4 floats (2KB)
#define SMEM_BYTES 200704

// ---- device globals (no allocation allowed) ----
__device__ __nv_bfloat16 g_zi[BATCH * DIM];
__device__ __nv_bfloat16 g_zj[BATCH * DIM];
__device__ float g_diag[BATCH];
__device__ float g_pm[2][BATCH];
__device__ float g_ps[2][BATCH];
__device__ float g_loss_sum;
__device__ float g_diag_sum;

// ================= PTX helpers =================
__device__ __forceinline__ uint32_t smem_u32(const void* p) {
    uint32_t a;
    asm("{ .reg .u64 t; cvta.to.shared.u64 t, %1; cvt.u32.u64 %0, t; }" : "=r"(a) : "l"(p));
    return a;
}
__device__ __forceinline__ float ex2f(float x) {
    float r; asm("ex2.approx.f32 %0, %1;" : "=f"(r) : "f"(x)); return r;
}
__device__ __forceinline__ void cp16(uint32_t dst, const void* src) {
    asm volatile("cp.async.cg.shared.global [%0], [%1], 16;" :: "r"(dst), "l"(src) : "memory");
}
__device__ __forceinline__ void cp_commit() { asm volatile("cp.async.commit_group;" ::: "memory"); }
template <int N> __device__ __forceinline__ void cp_wait() {
    asm volatile("cp.async.wait_group %0;" :: "n"(N) : "memory");
}
__device__ __forceinline__ void ldsm_x4(uint32_t* r, uint32_t addr) {
    asm volatile("ldmatrix.sync.aligned.m8n8.x4.shared.b16 {%0,%1,%2,%3}, [%4];\n"
                 : "=r"(r[0]), "=r"(r[1]), "=r"(r[2]), "=r"(r[3])
                 : "r"(addr));
}
__device__ __forceinline__ void mma_bf16(float* d, const uint32_t* a, const uint32_t* b) {
    asm volatile(
        "mma.sync.aligned.m16n8k16.row.col.f32.bf16.bf16.f32 "
        "{%0,%1,%2,%3}, {%4,%5,%6,%7}, {%8,%9}, {%0,%1,%2,%3};\n"
        : "+f"(d[0]), "+f"(d[1]), "+f"(d[2]), "+f"(d[3])
        : "r"(a[0]), "r"(a[1]), "r"(a[2]), "r"(a[3]), "r"(b[0]), "r"(b[1]));
}

// load a 128x256 bf16 tile into swizzled smem via cp.async
// layout: row r (512B), 16B chunk c stored at r*512 + ((c ^ (r&7))<<4)
__device__ __forceinline__ void load_tile(uint32_t dst, const __nv_bfloat16* src, int tid) {
    const char* s = (const char*)src;
    #pragma unroll
    for (int i = 0; i < 16; i++) {
        int idx = tid + i * THREADS;       // 0..4095
        int r = idx >> 5;                  // row 0..127
        int c = idx & 31;                  // 16B chunk 0..31
        uint32_t d = dst + r * 512 + (((c ^ (r & 7))) << 4);
        cp16(d, s + (size_t)r * 512 + (size_t)c * 16);
    }
}

// ================= kernels =================
__global__ void cl_init_kernel() {
    g_diag_sum = 0.0f;
    g_loss_sum = 0.0f;
}

// normalize + bf16 convert + exact fp32 diagonal; one block per row
__global__ void cl_prep_kernel(const float* __restrict__ p1,
                               const float* __restrict__ p2) {
    int row = blockIdx.x;
    int t = threadIdx.x;

    float v1 = p1[row * DIM + t];
    float v2 = p2[row * DIM + t];

    float s1 = v1 * v1, s2 = v2 * v2, s3 = v1 * v2;
    #pragma unroll
    for (int o = 16; o > 0; o >>= 1) {
        s1 += __shfl_down_sync(0xffffffffu, s1, o);
        s2 += __shfl_down_sync(0xffffffffu, s2, o);
        s3 += __shfl_down_sync(0xffffffffu, s3, o);
    }
    __shared__ float sh1[8], sh2[8], sh3[8];
    __shared__ float rn1, rn2, rdot;
    int wid = t >> 5;
    if ((t & 31) == 0) { sh1[wid] = s1; sh2[wid] = s2; sh3[wid] = s3; }
    __syncthreads();
    if (t == 0) {
        float a = 0.f, b = 0.f, c = 0.f;
        #pragma unroll
        for (int i = 0; i < 8; i++) { a += sh1[i]; b += sh2[i]; c += sh3[i]; }
        rn1 = fmaxf(sqrtf(a), 1e-12f);
        rn2 = fmaxf(sqrtf(b), 1e-12f);
        rdot = c;
    }
    __syncthreads();
    float n1 = rn1, n2 = rn2;
    g_zi[row * DIM + t] = __float2bfloat16(v1 / n1);
    g_zj[row * DIM + t] = __float2bfloat16(v2 / n2);
    if (t == 0) g_diag[row] = rdot / (n1 * n2);
}

// fused mma.sync GEMM + online LSE. grid = 128 (64 row-blocks x 2 col-halves)
// 8 warps as 2x4 over the 128x128 tile -> warp tile 64x32
__global__ void __launch_bounds__(THREADS, 1)
cl_main_kernel() {
    extern __shared__ char smem[];
    uint32_t sb = smem_u32(smem);
    const int tid  = threadIdx.x;
    const int warp = tid >> 5;
    const int lane = tid & 31;
    const int warp_m = warp >> 2;       // 0..1 : 64 rows
    const int warp_n = warp & 3;        // 0..3 : 32 cols
    const int rb   = (blockIdx.x >> 1) * BM;
    const int ch   = blockIdx.x & 1;
    const int col0 = ch * COLSPER;

    // prologue: A + B0 (group 0), B1 (group 1)
    load_tile(sb + SA,  g_zi + (size_t)rb * DIM, tid);
    load_tile(sb + SB0, g_zj + (size_t)col0 * DIM, tid);
    cp_commit();
    load_tile(sb + SB1, g_zj + (size_t)(col0 + BN) * DIM, tid);
    cp_commit();
    cp_wait<1>();
    __syncthreads();

    // per-thread online LSE state: 8 row-slots (mi 0..3 x half 0..1)
    float m_run[8], s_run[8];
    #pragma unroll
    for (int i = 0; i < 8; i++) { m_run[i] = -2.0f; s_run[i] = 0.0f; }

    // precomputed ldsm row bases
    uint32_t a_rowbase[4];
    #pragma unroll
    for (int mi = 0; mi < 4; mi++) {
        int row = warp_m * 64 + mi * 16 + (lane & 15);
        a_rowbase[mi] = sb + SA + row * 512 + ((row & 7) << 7);   // fold row into addr; chunk xor applied per-ks
    }
    // recompute exactly like round-1 (validated): addr = base_tile + row*512 + ((chk ^ (row&7))<<4)

    for (int t = 0; t < TILES; ++t) {
        const int sel = t & 1;
        const uint32_t bbase = sb + (sel ? SB1 : SB0);

        float acc[4][4][4];
        #pragma unroll
        for (int mi = 0; mi < 4; mi++)
            #pragma unroll
            for (int ni = 0; ni < 4; ni++)
                #pragma unroll
                for (int q = 0; q < 4; q++)
                    acc[mi][ni][q] = 0.0f;

        #pragma unroll
        for (int ks = 0; ks < 16; ks++) {
            uint32_t a[4][4];
            #pragma unroll
            for (int mi = 0; mi < 4; mi++) {
                int row = warp_m * 64 + mi * 16 + (lane & 15);
                int chk = ks * 2 + (lane >> 4);
                ldsm_x4(a[mi], sb + SA + row * 512 + ((chk ^ (row & 7)) << 4));
            }
            uint32_t b[4][2];
            #pragma unroll
            for (int np = 0; np < 2; np++) {
                int col = warp_n * 32 + np * 16 + (lane & 7) + ((lane >> 4) << 3);
                int chk = ks * 2 + ((lane >> 3) & 1);
                uint32_t r4[4];
                ldsm_x4(r4, bbase + col * 512 + ((chk ^ (col & 7)) << 4));
                b[np * 2][0] = r4[0];     b[np * 2][1] = r4[1];
                b[np * 2 + 1][0] = r4[2]; b[np * 2 + 1][1] = r4[3];
            }
            #pragma unroll
            for (int mi = 0; mi < 4; mi++)
                #pragma unroll
                for (int ni = 0; ni < 4; ni++)
                    mma_bf16(acc[mi][ni], a[mi], b[ni]);
        }

        __syncthreads();   // all warps done reading Bs[sel]

        // prefetch B[t+2] into the buffer just freed; overlaps epilogue + next tile
        if (t + 2 < TILES) {
            load_tile(bbase, g_zj + (size_t)(col0 + (t + 2) * BN) * DIM, tid);
            cp_commit();
        }

        // ---- epilogue: online LSE update on 64 values (8 rows x 8 cols) ----
        #pragma unroll
        for (int mi = 0; mi < 4; mi++) {
            #pragma unroll
            for (int h = 0; h < 2; h++) {
                int idx = mi * 2 + h;
                float y[8];
                #pragma unroll
                for (int ni = 0; ni < 4; ni++) {
                    y[ni * 2]     = acc[mi][ni][h * 2];
                    y[ni * 2 + 1] = acc[mi][ni][h * 2 + 1];
                }
                float tm = y[0];
                #pragma unroll
                for (int j = 1; j < 8; j++) tm = fmaxf(tm, y[j]);
                float nm = fmaxf(m_run[idx], tm);
                float nb = -nm * SCALE_L2;
                float a0 = 0.f;
                #pragma unroll
                for (int j = 0; j < 8; j++) a0 += ex2f(fmaf(y[j], SCALE_L2, nb));
                s_run[idx] = s_run[idx] * ex2f(fmaf(m_run[idx], SCALE_L2, nb)) + a0;
                m_run[idx] = nm;
            }
        }

        if (t + 2 < TILES) cp_wait<1>(); else cp_wait<0>();
        __syncthreads();
    }

    // ---- reduce across lanes sharing a row (lane&3 varies) ----
    #pragma unroll
    for (int idx = 0; idx < 8; idx++) {
        #pragma unroll
        for (int o = 1; o <= 2; o <<= 1) {
            float om = __shfl_xor_sync(0xffffffffu, m_run[idx], o);
            float os = __shfl_xor_sync(0xffffffffu, s_run[idx], o);
            float nm = fmaxf(m_run[idx], om);
            s_run[idx] = s_run[idx] * ex2f((m_run[idx] - nm) * SCALE_L2)
                       + os         * ex2f((om         - nm) * SCALE_L2);
            m_run[idx] = nm;
        }
    }

    // ---- merge across the 4 column-warps via smem ----
    float* mrg_m = (float*)(smem + SMRG_M);
    float* mrg_s = (float*)(smem + SMRG_S);
    if ((lane & 3) == 0) {
        #pragma unroll
        for (int idx = 0; idx < 8; idx++) {
            int row = warp_m * 64 + (idx >> 1) * 16 + (idx & 1) * 8 + (lane >> 2);
            mrg_m[row * 4 + warp_n] = m_run[idx];
            mrg_s[row * 4 + warp_n] = s_run[idx];
        }
    }
    __syncthreads();

    if (tid < BM) {
        int row = tid;
        float m = mrg_m[row * 4];
        #pragma unroll
        for (int w = 1; w < 4; w++) m = fmaxf(m, mrg_m[row * 4 + w]);
        float s = 0.0f;
        #pragma unroll
        for (int w = 0; w < 4; w++)
            s += mrg_s[row * 4 + w] * ex2f((mrg_m[row * 4 + w] - m) * SCALE_L2);
        g_pm[ch][rb + row] = m;
        g_ps[ch][rb + row] = s;
    }
}

// merge the 2 column-half partials per row, reduce loss + diag sums
__global__ void cl_merge_kernel() {
    int r = blockIdx.x * 256 + threadIdx.x;
    float m0 = g_pm[0][r], m1 = g_pm[1][r];
    float s0 = g_ps[0][r], s1 = g_ps[1][r];
    float m = fmaxf(m0, m1);
    float s = s0 * ex2f((m0 - m) * SCALE_L2) + s1 * ex2f((m1 - m) * SCALE_L2);
    float d = g_diag[r];
    float loss = 1000.0f * (m - d) + log2f(s) * LN2F;
    float ds = d;
    #pragma unroll
    for (int o = 16; o; o >>= 1) {
        loss += __shfl_down_sync(0xffffffffu, loss, o);
        ds   += __shfl_down_sync(0xffffffffu, ds, o);
    }
    __shared__ float sl[8], sd[8];
    if ((threadIdx.x & 31) == 0) { sl[threadIdx.x >> 5] = loss; sd[threadIdx.x >> 5] = ds; }
    __syncthreads();
    if (threadIdx.x == 0) {
        float L = 0.f, D = 0.f;
        #pragma unroll
        for (int i = 0; i < 8; i++) { L += sl[i]; D += sd[i]; }
        atomicAdd(&g_loss_sum, L);
        atomicAdd(&g_diag_sum, D);
    }
}

__global__ void cl_fin_kernel(float* out, int out_size) {
    if (out_size > 0) out[0] = g_loss_sum / (float)BATCH;
    if (out_size > 1) out[1] = g_diag_sum;
}

// ================= launch =================
extern "C" void kernel_launch(void* const* d_in, const int* in_sizes, int n_in,
                              void* d_out, int out_size) {
    const float* p1 = (const float*)d_in[0];
    const float* p2 = (const float*)d_in[1];
    float* out = (float*)d_out;

    cudaFuncSetAttribute(cl_main_kernel,
                         cudaFuncAttributeMaxDynamicSharedMemorySize, SMEM_BYTES);

    cl_init_kernel<<<1, 1>>>();
    cl_prep_kernel<<<BATCH, DIM>>>(p1, p2);
    cl_main_kernel<<<128, THREADS, SMEM_BYTES>>>();
    cl_merge_kernel<<<BATCH / 256, 256>>>();
    cl_fin_kernel<<<1, 1>>>(out, out_size);
}

// round 4
// speedup vs baseline: 2.3142x; 1.4007x over previous
#include <cuda_runtime.h>
#include <cuda_bf16.h>
#include <cstdint>
#include <math.h>

#define BATCH 8192
#define DIM   256
#define BM    128
#define BN    128
#define COLSPER 4096
#define TILES (COLSPER / BN)      // 32
#define THREADS 256

#define SCALE_L2 1442.6950408889634f   // 1000 * log2(e)
#define LN2F     0.69314718055994531f
#define MAGICF   12582912.0f           // 2^23 + 2^22
#define MAGICI   0x4B400000

// ---- shared memory layout (dynamic) ----
#define SA     0                        // A tile 128x256 int8 (32KB, swizzled)
#define SB0    32768                    // B tile buf0 (32KB)
#define SB1    65536                    // B tile buf1 (32KB)
#define SMRG_M 98304                    // 128*4 floats (2KB)
#define SMRG_S 100352                   // 128*4 floats (2KB)
#define SMEM_BYTES 102400

// ---- device globals (no allocation allowed) ----
__device__ uint32_t g_zi8[BATCH * DIM / 4];   // packed int8
__device__ uint32_t g_zj8[BATCH * DIM / 4];
__device__ float g_n1[BATCH];
__device__ float g_n2[BATCH];
__device__ float g_diag[BATCH];
__device__ float g_pm[2][BATCH];
__device__ float g_ps[2][BATCH];
__device__ unsigned int g_absmax_bits;
__device__ float g_loss_sum;
__device__ float g_diag_sum;

// ================= PTX helpers =================
__device__ __forceinline__ uint32_t smem_u32(const void* p) {
    uint32_t a;
    asm("{ .reg .u64 t; cvta.to.shared.u64 t, %1; cvt.u32.u64 %0, t; }" : "=r"(a) : "l"(p));
    return a;
}
__device__ __forceinline__ float ex2f(float x) {
    float r; asm("ex2.approx.f32 %0, %1;" : "=f"(r) : "f"(x)); return r;
}
__device__ __forceinline__ void cp16(uint32_t dst, const void* src) {
    asm volatile("cp.async.cg.shared.global [%0], [%1], 16;" :: "r"(dst), "l"(src) : "memory");
}
__device__ __forceinline__ void cp_commit() { asm volatile("cp.async.commit_group;" ::: "memory"); }
template <int N> __device__ __forceinline__ void cp_wait() {
    asm volatile("cp.async.wait_group %0;" :: "n"(N) : "memory");
}
__device__ __forceinline__ void ldsm_x4(uint32_t* r, uint32_t addr) {
    asm volatile("ldmatrix.sync.aligned.m8n8.x4.shared.b16 {%0,%1,%2,%3}, [%4];\n"
                 : "=r"(r[0]), "=r"(r[1]), "=r"(r[2]), "=r"(r[3])
                 : "r"(addr));
}
__device__ __forceinline__ void mma_s8(int* d, const uint32_t* a, const uint32_t* b) {
    asm volatile(
        "mma.sync.aligned.m16n8k32.row.col.s32.s8.s8.s32 "
        "{%0,%1,%2,%3}, {%4,%5,%6,%7}, {%8,%9}, {%0,%1,%2,%3};\n"
        : "+r"(d[0]), "+r"(d[1]), "+r"(d[2]), "+r"(d[3])
        : "r"(a[0]), "r"(a[1]), "r"(a[2]), "r"(a[3]), "r"(b[0]), "r"(b[1]));
}

// swizzled chunk position inside a 256B row: chunk c in 0..15
__device__ __forceinline__ uint32_t chunk_pos(int r, int c) {
    return (uint32_t)(((c & 8) | ((c ^ r) & 7)) << 4);
}

// load a 128x256 int8 tile (32KB) into swizzled smem via cp.async
__device__ __forceinline__ void load_tile(uint32_t dst, const uint32_t* src, int tid) {
    const char* s = (const char*)src;
    #pragma unroll
    for (int i = 0; i < 8; i++) {
        int idx = tid + i * THREADS;       // 0..2047
        int r = idx >> 4;                  // row 0..127
        int c = idx & 15;                  // 16B chunk 0..15
        cp16(dst + r * 256 + chunk_pos(r, c), s + (size_t)r * 256 + (size_t)c * 16);
    }
}

// ================= kernels =================
__global__ void cl_init_kernel() {
    g_diag_sum = 0.0f;
    g_loss_sum = 0.0f;
    g_absmax_bits = 0u;
}

// pass 1: row norms, exact fp32 diagonal, global max |z| (post-normalize)
__global__ void cl_prep_kernel(const float* __restrict__ p1,
                               const float* __restrict__ p2) {
    int row = blockIdx.x;
    int t = threadIdx.x;

    float v1 = p1[row * DIM + t];
    float v2 = p2[row * DIM + t];

    float s1 = v1 * v1, s2 = v2 * v2, s3 = v1 * v2;
    #pragma unroll
    for (int o = 16; o > 0; o >>= 1) {
        s1 += __shfl_down_sync(0xffffffffu, s1, o);
        s2 += __shfl_down_sync(0xffffffffu, s2, o);
        s3 += __shfl_down_sync(0xffffffffu, s3, o);
    }
    __shared__ float sh1[8], sh2[8], sh3[8], shm[8];
    __shared__ float rn1, rn2;
    int wid = t >> 5;
    if ((t & 31) == 0) { sh1[wid] = s1; sh2[wid] = s2; sh3[wid] = s3; }
    __syncthreads();
    if (t == 0) {
        float a = 0.f, b = 0.f, c = 0.f;
        #pragma unroll
        for (int i = 0; i < 8; i++) { a += sh1[i]; b += sh2[i]; c += sh3[i]; }
        float n1 = fmaxf(sqrtf(a), 1e-12f);
        float n2 = fmaxf(sqrtf(b), 1e-12f);
        rn1 = n1; rn2 = n2;
        g_n1[row] = n1;
        g_n2[row] = n2;
        g_diag[row] = c / (n1 * n2);
    }
    __syncthreads();
    // block max of |z| after normalization
    float mx = fmaxf(fabsf(v1) / rn1, fabsf(v2) / rn2);
    #pragma unroll
    for (int o = 16; o > 0; o >>= 1)
        mx = fmaxf(mx, __shfl_down_sync(0xffffffffu, mx, o));
    if ((t & 31) == 0) shm[wid] = mx;
    __syncthreads();
    if (t == 0) {
        float m = shm[0];
        #pragma unroll
        for (int i = 1; i < 8; i++) m = fmaxf(m, shm[i]);
        atomicMax(&g_absmax_bits, __float_as_uint(m));   // positive floats: bit-monotone
    }
}

// pass 2: quantize both tensors to int8 with the exact global scale
__global__ void cl_quant_kernel(const float* __restrict__ p1,
                                const float* __restrict__ p2) {
    int g = blockIdx.x * 256 + threadIdx.x;       // 0 .. 524287 (one float4 per tensor)
    int row = g >> 6;
    float S = __uint_as_float(g_absmax_bits);
    float q = 127.0f / S;
    float q1 = q / g_n1[row];
    float q2 = q / g_n2[row];

    float4 a = ((const float4*)p1)[g];
    float4 b = ((const float4*)p2)[g];

    int a0 = __float2int_rn(a.x * q1), a1 = __float2int_rn(a.y * q1);
    int a2 = __float2int_rn(a.z * q1), a3 = __float2int_rn(a.w * q1);
    int b0 = __float2int_rn(b.x * q2), b1 = __float2int_rn(b.y * q2);
    int b2 = __float2int_rn(b.z * q2), b3 = __float2int_rn(b.w * q2);

    g_zi8[g] = (a0 & 0xff) | ((a1 & 0xff) << 8) | ((a2 & 0xff) << 16) | (a3 << 24);
    g_zj8[g] = (b0 & 0xff) | ((b1 & 0xff) << 8) | ((b2 & 0xff) << 16) | (b3 << 24);
}

// fused int8 IMMA GEMM + online LSE. grid = 128 (64 row-blocks x 2 col-halves)
// 8 warps as 2x4 over the 128x128 tile -> warp tile 64x32
__global__ void __launch_bounds__(THREADS, 1)
cl_main_kernel() {
    extern __shared__ char smem[];
    uint32_t sb = smem_u32(smem);
    const int tid  = threadIdx.x;
    const int warp = tid >> 5;
    const int lane = tid & 31;
    const int warp_m = warp >> 2;       // 0..1 : 64 rows
    const int warp_n = warp & 3;        // 0..3 : 32 cols
    const int rb   = (blockIdx.x >> 1) * BM;
    const int ch   = blockIdx.x & 1;
    const int col0 = ch * COLSPER;

    // log-domain scale: y_log2 = dot_int * kk
    const float S = __uint_as_float(g_absmax_bits);
    const float kk = SCALE_L2 * (S * S) * (1.0f / 16129.0f);

    // prologue: A + B0 (group 0), B1 (group 1)
    load_tile(sb + SA,  g_zi8 + (size_t)rb * (DIM / 4), tid);
    load_tile(sb + SB0, g_zj8 + (size_t)col0 * (DIM / 4), tid);
    cp_commit();
    load_tile(sb + SB1, g_zj8 + (size_t)(col0 + BN) * (DIM / 4), tid);
    cp_commit();
    cp_wait<1>();
    __syncthreads();

    // per-thread online LSE state (int-units): 8 row-slots
    float m_run[8], s_run[8];
    #pragma unroll
    for (int i = 0; i < 8; i++) { m_run[i] = -1.0e9f; s_run[i] = 0.0f; }

    const int mrow = lane & 7;
    const int am = lane >> 3;           // ldsm matrix id

    for (int t = 0; t < TILES; ++t) {
        const int sel = t & 1;
        const uint32_t bbase = sb + (sel ? SB1 : SB0);

        int acc[4][4][4];
        #pragma unroll
        for (int mi = 0; mi < 4; mi++)
            #pragma unroll
            for (int ni = 0; ni < 4; ni++)
                #pragma unroll
                for (int q = 0; q < 4; q++)
                    acc[mi][ni][q] = 0;

        #pragma unroll
        for (int ks = 0; ks < 8; ks++) {
            // A fragments: matrices {r0-7 c2k, r8-15 c2k, r0-7 c2k+1, r8-15 c2k+1}
            uint32_t a[4][4];
            {
                int achk = 2 * ks + (am >> 1);
                #pragma unroll
                for (int mi = 0; mi < 4; mi++) {
                    int row = warp_m * 64 + mi * 16 + ((am & 1) << 3) + mrow;
                    ldsm_x4(a[mi], sb + SA + row * 256 + chunk_pos(row, achk));
                }
            }
            // B fragments: matrices {n0-7 c2k, n0-7 c2k+1, n8-15 c2k, n8-15 c2k+1}
            uint32_t b[4][2];
            {
                int bchk = 2 * ks + (am & 1);
                #pragma unroll
                for (int np = 0; np < 2; np++) {
                    int col = warp_n * 32 + np * 16 + ((am >> 1) << 3) + mrow;
                    uint32_t r4[4];
                    ldsm_x4(r4, bbase + col * 256 + chunk_pos(col, bchk));
                    b[np * 2][0] = r4[0];     b[np * 2][1] = r4[1];
                    b[np * 2 + 1][0] = r4[2]; b[np * 2 + 1][1] = r4[3];
                }
            }
            #pragma unroll
            for (int mi = 0; mi < 4; mi++)
                #pragma unroll
                for (int ni = 0; ni < 4; ni++)
                    mma_s8(acc[mi][ni], a[mi], b[ni]);
        }

        __syncthreads();   // all warps done reading Bs[sel]

        // prefetch B[t+2] into the freed buffer; overlaps epilogue + next tile
        if (t + 2 < TILES) {
            load_tile(bbase, g_zj8 + (size_t)(col0 + (t + 2) * BN) * (DIM / 4), tid);
            cp_commit();
        }

        // ---- epilogue: online LSE update, 8 rows x 8 cols of int32 ----
        #pragma unroll
        for (int mi = 0; mi < 4; mi++) {
            #pragma unroll
            for (int h = 0; h < 2; h++) {
                int idx = mi * 2 + h;
                int y[8];
                #pragma unroll
                for (int ni = 0; ni < 4; ni++) {
                    y[ni * 2]     = acc[mi][ni][h * 2];
                    y[ni * 2 + 1] = acc[mi][ni][h * 2 + 1];
                }
                int tmi = y[0];
                #pragma unroll
                for (int j = 1; j < 8; j++) tmi = max(tmi, y[j]);
                float nm = fmaxf(m_run[idx], (float)tmi);
                float nb = -(nm + MAGICF) * kk;       // folds int->float magic bias
                float a0 = 0.f;
                #pragma unroll
                for (int j = 0; j < 8; j++)
                    a0 += ex2f(fmaf(__int_as_float(y[j] + MAGICI), kk, nb));
                s_run[idx] = s_run[idx] * ex2f((m_run[idx] - nm) * kk) + a0;
                m_run[idx] = nm;
            }
        }

        if (t + 2 < TILES) cp_wait<1>(); else cp_wait<0>();
        __syncthreads();
    }

    // ---- reduce across lanes sharing a row (lane&3 varies) ----
    #pragma unroll
    for (int idx = 0; idx < 8; idx++) {
        #pragma unroll
        for (int o = 1; o <= 2; o <<= 1) {
            float om = __shfl_xor_sync(0xffffffffu, m_run[idx], o);
            float os = __shfl_xor_sync(0xffffffffu, s_run[idx], o);
            float nm = fmaxf(m_run[idx], om);
            s_run[idx] = s_run[idx] * ex2f((m_run[idx] - nm) * kk)
                       + os         * ex2f((om         - nm) * kk);
            m_run[idx] = nm;
        }
    }

    // ---- merge across the 4 column-warps via smem ----
    float* mrg_m = (float*)(smem + SMRG_M);
    float* mrg_s = (float*)(smem + SMRG_S);
    if ((lane & 3) == 0) {
        #pragma unroll
        for (int idx = 0; idx < 8; idx++) {
            int row = warp_m * 64 + (idx >> 1) * 16 + (idx & 1) * 8 + (lane >> 2);
            mrg_m[row * 4 + warp_n] = m_run[idx];
            mrg_s[row * 4 + warp_n] = s_run[idx];
        }
    }
    __syncthreads();

    if (tid < BM) {
        int row = tid;
        float m = mrg_m[row * 4];
        #pragma unroll
        for (int w = 1; w < 4; w++) m = fmaxf(m, mrg_m[row * 4 + w]);
        float s = 0.0f;
        #pragma unroll
        for (int w = 0; w < 4; w++)
            s += mrg_s[row * 4 + w] * ex2f((mrg_m[row * 4 + w] - m) * kk);
        g_pm[ch][rb + row] = m;
        g_ps[ch][rb + row] = s;
    }
}

// merge the 2 column-half partials per row, reduce loss + diag sums
__global__ void cl_merge_kernel() {
    int r = blockIdx.x * 256 + threadIdx.x;
    float S = __uint_as_float(g_absmax_bits);
    float kk = SCALE_L2 * (S * S) * (1.0f / 16129.0f);

    float m0 = g_pm[0][r], m1 = g_pm[1][r];
    float s0 = g_ps[0][r], s1 = g_ps[1][r];
    float m = fmaxf(m0, m1);
    float s = s0 * ex2f((m0 - m) * kk) + s1 * ex2f((m1 - m) * kk);
    float d = g_diag[r];
    float loss = LN2F * fmaf(m, kk, log2f(s)) - 1000.0f * d;
    float ds = d;
    #pragma unroll
    for (int o = 16; o; o >>= 1) {
        loss += __shfl_down_sync(0xffffffffu, loss, o);
        ds   += __shfl_down_sync(0xffffffffu, ds, o);
    }
    __shared__ float sl[8], sd[8];
    if ((threadIdx.x & 31) == 0) { sl[threadIdx.x >> 5] = loss; sd[threadIdx.x >> 5] = ds; }
    __syncthreads();
    if (threadIdx.x == 0) {
        float L = 0.f, D = 0.f;
        #pragma unroll
        for (int i = 0; i < 8; i++) { L += sl[i]; D += sd[i]; }
        atomicAdd(&g_loss_sum, L);
        atomicAdd(&g_diag_sum, D);
    }
}

__global__ void cl_fin_kernel(float* out, int out_size) {
    if (out_size > 0) out[0] = g_loss_sum / (float)BATCH;
    if (out_size > 1) out[1] = g_diag_sum;
}

// ================= launch =================
extern "C" void kernel_launch(void* const* d_in, const int* in_sizes, int n_in,
                              void* d_out, int out_size) {
    const float* p1 = (const float*)d_in[0];
    const float* p2 = (const float*)d_in[1];
    float* out = (float*)d_out;

    cudaFuncSetAttribute(cl_main_kernel,
                         cudaFuncAttributeMaxDynamicSharedMemorySize, SMEM_BYTES);

    cl_init_kernel<<<1, 1>>>();
    cl_prep_kernel<<<BATCH, DIM>>>(p1, p2);
    cl_quant_kernel<<<BATCH * DIM / 4 / 256, 256>>>(p1, p2);
    cl_main_kernel<<<128, THREADS, SMEM_BYTES>>>();
    cl_merge_kernel<<<BATCH / 256, 256>>>();
    cl_fin_kernel<<<1, 1>>>(out, out_size);
}